// round 1
// baseline (speedup 1.0000x reference)
#include <cuda_runtime.h>
#include <math.h>

// Problem constants
#define B_   2
#define S_   1024
#define D_   1024
#define E_   8
#define KTOP 2
#define FF_  2048
#define T_   (B_ * S_)        // 2048 tokens
#define OUT_MAIN (T_ * D_)    // 2,097,152 floats for `output`
#define OUT_FULL (OUT_MAIN + T_*E_ + T_*KTOP + T_*KTOP)  // + probs + idx + weights

// Device scratch (allocation-free: static device globals)
__device__ int   g_cnt[E_];
__device__ int   g_tok[E_ * T_];     // per-expert token lists (capacity T_ each)
__device__ float g_wt [E_ * T_];     // matching combine weights
__device__ float g_h  [(size_t)E_ * T_ * FF_];   // expert hidden activations

// ---------------------------------------------------------------------------
// Zero output + reset counters
// ---------------------------------------------------------------------------
__global__ void zero_kernel(float* __restrict__ out, int n) {
    int i = blockIdx.x * blockDim.x + threadIdx.x;
    if (i < n) out[i] = 0.0f;
    if (blockIdx.x == 0 && threadIdx.x < E_) g_cnt[threadIdx.x] = 0;
}

// ---------------------------------------------------------------------------
// Router: logits -> softmax -> top-2 -> renormalize -> bucket by expert
// One block per token, 256 threads (8 warps == 8 experts).
// ---------------------------------------------------------------------------
__global__ void router_kernel(const float* __restrict__ x,
                              const float* __restrict__ rw,
                              float* __restrict__ out, int out_size) {
    const int t = blockIdx.x;
    __shared__ float xs[D_];
    __shared__ float logits[E_];

    for (int i = threadIdx.x; i < D_; i += blockDim.x)
        xs[i] = x[(size_t)t * D_ + i];
    __syncthreads();

    const int w = threadIdx.x >> 5;     // warp id == expert id
    const int lane = threadIdx.x & 31;
    float s = 0.0f;
    const float* rwe = rw + (size_t)w * D_;
    for (int k = lane; k < D_; k += 32) s += xs[k] * rwe[k];
    #pragma unroll
    for (int o = 16; o; o >>= 1) s += __shfl_xor_sync(0xffffffffu, s, o);
    if (lane == 0) logits[w] = s;
    __syncthreads();

    if (threadIdx.x == 0) {
        float mx = logits[0];
        #pragma unroll
        for (int e = 1; e < E_; e++) mx = fmaxf(mx, logits[e]);
        float p[E_]; float sum = 0.0f;
        #pragma unroll
        for (int e = 0; e < E_; e++) { p[e] = expf(logits[e] - mx); sum += p[e]; }
        float inv = 1.0f / sum;
        #pragma unroll
        for (int e = 0; e < E_; e++) p[e] *= inv;

        // top-2 (lowest index wins ties, matching jax.lax.top_k)
        int i0 = 0;
        #pragma unroll
        for (int e = 1; e < E_; e++) if (p[e] > p[i0]) i0 = e;
        int i1 = (i0 == 0) ? 1 : 0;
        #pragma unroll
        for (int e = 0; e < E_; e++) if (e != i0 && p[e] > p[i1]) i1 = e;

        float w0 = p[i0], w1 = p[i1];
        float rinv = 1.0f / (w0 + w1);
        w0 *= rinv; w1 *= rinv;

        int s0 = atomicAdd(&g_cnt[i0], 1);
        g_tok[i0 * T_ + s0] = t; g_wt[i0 * T_ + s0] = w0;
        int s1 = atomicAdd(&g_cnt[i1], 1);
        g_tok[i1 * T_ + s1] = t; g_wt[i1 * T_ + s1] = w1;

        if (out_size >= OUT_FULL) {
            float* probs = out + OUT_MAIN;
            float* idxs  = out + OUT_MAIN + T_ * E_;
            float* wts   = out + OUT_MAIN + T_ * E_ + T_ * KTOP;
            #pragma unroll
            for (int e = 0; e < E_; e++) probs[t * E_ + e] = p[e];
            idxs[t * KTOP + 0] = (float)i0;
            idxs[t * KTOP + 1] = (float)i1;
            wts [t * KTOP + 0] = w0;
            wts [t * KTOP + 1] = w1;
        }
    }
}

// ---------------------------------------------------------------------------
// GEMM1: per expert e, H[s, n] = silu( sum_k X[tok(s), k] * W1[e, n, k] )
// Tiles: 64x64x16, 256 threads, 4x4 microtile per thread.
// ---------------------------------------------------------------------------
__global__ void expert_gemm1(const float* __restrict__ x,
                             const float* __restrict__ w1) {
    const int e = blockIdx.z;
    const int n_e = g_cnt[e];
    const int row0 = blockIdx.y * 64;
    if (row0 >= n_e) return;
    const int col0 = blockIdx.x * 64;

    __shared__ float As[16][64];
    __shared__ float Bs[16][64];
    __shared__ int   toks[64];

    const int tid = threadIdx.x;
    if (tid < 64) {
        int r = row0 + tid;
        toks[tid] = (r < n_e) ? g_tok[e * T_ + r] : -1;
    }
    __syncthreads();

    const float* Bg = w1 + (size_t)e * FF_ * D_;
    const int lr = tid >> 2;           // 0..63 row within tile
    const int lk = (tid & 3) * 4;      // k sub-offset
    const int ty = tid >> 4, tx = tid & 15;

    float acc[4][4] = {};
    const int tokr = toks[lr];

    for (int k0 = 0; k0 < D_; k0 += 16) {
        float4 av = make_float4(0.f, 0.f, 0.f, 0.f);
        if (tokr >= 0)
            av = *(const float4*)(x + (size_t)tokr * D_ + k0 + lk);
        As[lk+0][lr] = av.x; As[lk+1][lr] = av.y;
        As[lk+2][lr] = av.z; As[lk+3][lr] = av.w;

        float4 bv = *(const float4*)(Bg + (size_t)(col0 + lr) * D_ + k0 + lk);
        Bs[lk+0][lr] = bv.x; Bs[lk+1][lr] = bv.y;
        Bs[lk+2][lr] = bv.z; Bs[lk+3][lr] = bv.w;
        __syncthreads();

        #pragma unroll
        for (int k = 0; k < 16; k++) {
            float4 a = *(const float4*)&As[k][ty * 4];
            float4 b = *(const float4*)&Bs[k][tx * 4];
            acc[0][0] += a.x*b.x; acc[0][1] += a.x*b.y; acc[0][2] += a.x*b.z; acc[0][3] += a.x*b.w;
            acc[1][0] += a.y*b.x; acc[1][1] += a.y*b.y; acc[1][2] += a.y*b.z; acc[1][3] += a.y*b.w;
            acc[2][0] += a.z*b.x; acc[2][1] += a.z*b.y; acc[2][2] += a.z*b.z; acc[2][3] += a.z*b.w;
            acc[3][0] += a.w*b.x; acc[3][1] += a.w*b.y; acc[3][2] += a.w*b.z; acc[3][3] += a.w*b.w;
        }
        __syncthreads();
    }

    float* C = g_h + ((size_t)e * T_ + row0) * FF_;
    #pragma unroll
    for (int i = 0; i < 4; i++) {
        int r = ty * 4 + i;
        if (row0 + r < n_e) {
            float4 v;
            float a0 = acc[i][0], a1 = acc[i][1], a2 = acc[i][2], a3 = acc[i][3];
            v.x = a0 / (1.0f + expf(-a0));
            v.y = a1 / (1.0f + expf(-a1));
            v.z = a2 / (1.0f + expf(-a2));
            v.w = a3 / (1.0f + expf(-a3));
            *(float4*)&C[(size_t)r * FF_ + col0 + tx * 4] = v;
        }
    }
}

// ---------------------------------------------------------------------------
// GEMM2: per expert e, out[tok(s), n] += wt(s) * sum_k H[s,k] * W2[e, n, k]
// ---------------------------------------------------------------------------
__global__ void expert_gemm2(const float* __restrict__ w2,
                             float* __restrict__ out) {
    const int e = blockIdx.z;
    const int n_e = g_cnt[e];
    const int row0 = blockIdx.y * 64;
    if (row0 >= n_e) return;
    const int col0 = blockIdx.x * 64;

    __shared__ float As[16][64];
    __shared__ float Bs[16][64];
    __shared__ int   toks[64];
    __shared__ float wts[64];

    const int tid = threadIdx.x;
    if (tid < 64) {
        int r = row0 + tid;
        if (r < n_e) { toks[tid] = g_tok[e * T_ + r]; wts[tid] = g_wt[e * T_ + r]; }
        else         { toks[tid] = -1;                wts[tid] = 0.0f; }
    }
    __syncthreads();

    const float* Ag = g_h + ((size_t)e * T_ + row0) * FF_;
    const float* Bg = w2 + (size_t)e * D_ * FF_;
    const int lr = tid >> 2;
    const int lk = (tid & 3) * 4;
    const int ty = tid >> 4, tx = tid & 15;

    float acc[4][4] = {};

    for (int k0 = 0; k0 < FF_; k0 += 16) {
        float4 av = *(const float4*)(Ag + (size_t)lr * FF_ + k0 + lk);
        As[lk+0][lr] = av.x; As[lk+1][lr] = av.y;
        As[lk+2][lr] = av.z; As[lk+3][lr] = av.w;

        float4 bv = *(const float4*)(Bg + (size_t)(col0 + lr) * FF_ + k0 + lk);
        Bs[lk+0][lr] = bv.x; Bs[lk+1][lr] = bv.y;
        Bs[lk+2][lr] = bv.z; Bs[lk+3][lr] = bv.w;
        __syncthreads();

        #pragma unroll
        for (int k = 0; k < 16; k++) {
            float4 a = *(const float4*)&As[k][ty * 4];
            float4 b = *(const float4*)&Bs[k][tx * 4];
            acc[0][0] += a.x*b.x; acc[0][1] += a.x*b.y; acc[0][2] += a.x*b.z; acc[0][3] += a.x*b.w;
            acc[1][0] += a.y*b.x; acc[1][1] += a.y*b.y; acc[1][2] += a.y*b.z; acc[1][3] += a.y*b.w;
            acc[2][0] += a.z*b.x; acc[2][1] += a.z*b.y; acc[2][2] += a.z*b.z; acc[2][3] += a.z*b.w;
            acc[3][0] += a.w*b.x; acc[3][1] += a.w*b.y; acc[3][2] += a.w*b.z; acc[3][3] += a.w*b.w;
        }
        __syncthreads();
    }

    #pragma unroll
    for (int i = 0; i < 4; i++) {
        int r = ty * 4 + i;
        if (row0 + r < n_e) {
            int   t = toks[r];
            float w = wts[r];
            float* orow = out + (size_t)t * D_ + col0 + tx * 4;
            atomicAdd(&orow[0], w * acc[i][0]);
            atomicAdd(&orow[1], w * acc[i][1]);
            atomicAdd(&orow[2], w * acc[i][2]);
            atomicAdd(&orow[3], w * acc[i][3]);
        }
    }
}

// ---------------------------------------------------------------------------
extern "C" void kernel_launch(void* const* d_in, const int* in_sizes, int n_in,
                              void* d_out, int out_size) {
    const float* x  = (const float*)d_in[0];
    const float* rw = (const float*)d_in[1];
    const float* w1 = (const float*)d_in[2];
    const float* w2 = (const float*)d_in[3];
    float* out = (float*)d_out;

    zero_kernel<<<(out_size + 255) / 256, 256>>>(out, out_size);
    router_kernel<<<T_, 256>>>(x, rw, out, out_size);
    expert_gemm1<<<dim3(FF_ / 64, T_ / 64, E_), 256>>>(x, w1);
    expert_gemm2<<<dim3(D_ / 64, T_ / 64, E_), 256>>>(w2, out);
}

// round 2
// speedup vs baseline: 1.2887x; 1.2887x over previous
#include <cuda_runtime.h>
#include <math.h>

// Problem constants
#define B_   2
#define S_   1024
#define D_   1024
#define E_   8
#define KTOP 2
#define FF_  2048
#define T_   (B_ * S_)        // 2048 tokens
#define OUT_MAIN (T_ * D_)
#define OUT_FULL (OUT_MAIN + T_*E_ + T_*KTOP + T_*KTOP)

#define TILE 128
#define KT   16

// Device scratch (allocation-free: static device globals)
__device__ int   g_cnt[E_];
__device__ int   g_tok[E_ * T_];
__device__ float g_wt [E_ * T_];
__device__ float g_h  [(size_t)E_ * T_ * FF_];

// ---------------------------------------------------------------------------
__global__ void zero_kernel(float* __restrict__ out, int n) {
    int i = blockIdx.x * blockDim.x + threadIdx.x;
    if (i < n) out[i] = 0.0f;
    if (blockIdx.x == 0 && threadIdx.x < E_) g_cnt[threadIdx.x] = 0;
}

// ---------------------------------------------------------------------------
// Router: one block per token, 8 warps == 8 experts.
// ---------------------------------------------------------------------------
__global__ void router_kernel(const float* __restrict__ x,
                              const float* __restrict__ rw,
                              float* __restrict__ out, int out_size) {
    const int t = blockIdx.x;
    __shared__ float xs[D_];
    __shared__ float logits[E_];

    for (int i = threadIdx.x; i < D_; i += blockDim.x)
        xs[i] = x[(size_t)t * D_ + i];
    __syncthreads();

    const int w = threadIdx.x >> 5;
    const int lane = threadIdx.x & 31;
    float s = 0.0f;
    const float* rwe = rw + (size_t)w * D_;
    for (int k = lane; k < D_; k += 32) s += xs[k] * rwe[k];
    #pragma unroll
    for (int o = 16; o; o >>= 1) s += __shfl_xor_sync(0xffffffffu, s, o);
    if (lane == 0) logits[w] = s;
    __syncthreads();

    if (threadIdx.x == 0) {
        float mx = logits[0];
        #pragma unroll
        for (int e = 1; e < E_; e++) mx = fmaxf(mx, logits[e]);
        float p[E_]; float sum = 0.0f;
        #pragma unroll
        for (int e = 0; e < E_; e++) { p[e] = expf(logits[e] - mx); sum += p[e]; }
        float inv = 1.0f / sum;
        #pragma unroll
        for (int e = 0; e < E_; e++) p[e] *= inv;

        int i0 = 0;
        #pragma unroll
        for (int e = 1; e < E_; e++) if (p[e] > p[i0]) i0 = e;
        int i1 = (i0 == 0) ? 1 : 0;
        #pragma unroll
        for (int e = 0; e < E_; e++) if (e != i0 && p[e] > p[i1]) i1 = e;

        float w0 = p[i0], w1 = p[i1];
        float rinv = 1.0f / (w0 + w1);
        w0 *= rinv; w1 *= rinv;

        int s0 = atomicAdd(&g_cnt[i0], 1);
        g_tok[i0 * T_ + s0] = t; g_wt[i0 * T_ + s0] = w0;
        int s1 = atomicAdd(&g_cnt[i1], 1);
        g_tok[i1 * T_ + s1] = t; g_wt[i1 * T_ + s1] = w1;

        if (out_size >= OUT_FULL) {
            float* probs = out + OUT_MAIN;
            float* idxs  = out + OUT_MAIN + T_ * E_;
            float* wts   = out + OUT_MAIN + T_ * E_ + T_ * KTOP;
            #pragma unroll
            for (int e = 0; e < E_; e++) probs[t * E_ + e] = p[e];
            idxs[t * KTOP + 0] = (float)i0;
            idxs[t * KTOP + 1] = (float)i1;
            wts [t * KTOP + 0] = w0;
            wts [t * KTOP + 1] = w1;
        }
    }
}

// ---------------------------------------------------------------------------
// GEMM1: H[s,n] = silu( X[tok(s),:] . W1[e,n,:] )   128x128x16 tile, 8x8 micro
// ---------------------------------------------------------------------------
__global__ void __launch_bounds__(256, 2)
expert_gemm1(const float* __restrict__ x, const float* __restrict__ w1) {
    const int e = blockIdx.z;
    const int n_e = g_cnt[e];
    const int row0 = blockIdx.y * TILE;
    if (row0 >= n_e) return;
    const int col0 = blockIdx.x * TILE;

    __shared__ float As[KT][TILE];
    __shared__ float Bs[KT][TILE];
    __shared__ int   toks[TILE];

    const int tid = threadIdx.x;
    if (tid < TILE) {
        int r = row0 + tid;
        toks[tid] = (r < n_e) ? g_tok[e * T_ + r] : -1;
    }
    __syncthreads();

    const int lr = tid >> 2;            // 0..63
    const int lk = (tid & 3) * 4;       // k sub-offset
    const int tok0 = toks[lr];
    const int tok1 = toks[lr + 64];
    const float* Bg = w1 + (size_t)e * FF_ * D_;
    const float* brow0 = Bg + (size_t)(col0 + lr) * D_;
    const float* brow1 = Bg + (size_t)(col0 + lr + 64) * D_;

    const int ty = tid >> 4, tx = tid & 15;
    float acc[8][8] = {};

    for (int k0 = 0; k0 < D_; k0 += KT) {
        float4 a0 = make_float4(0.f,0.f,0.f,0.f), a1 = a0;
        if (tok0 >= 0) a0 = *(const float4*)(x + (size_t)tok0 * D_ + k0 + lk);
        if (tok1 >= 0) a1 = *(const float4*)(x + (size_t)tok1 * D_ + k0 + lk);
        float4 b0 = *(const float4*)(brow0 + k0 + lk);
        float4 b1 = *(const float4*)(brow1 + k0 + lk);

        __syncthreads();   // previous iteration's compute done
        As[lk+0][lr] = a0.x; As[lk+1][lr] = a0.y; As[lk+2][lr] = a0.z; As[lk+3][lr] = a0.w;
        As[lk+0][lr+64] = a1.x; As[lk+1][lr+64] = a1.y; As[lk+2][lr+64] = a1.z; As[lk+3][lr+64] = a1.w;
        Bs[lk+0][lr] = b0.x; Bs[lk+1][lr] = b0.y; Bs[lk+2][lr] = b0.z; Bs[lk+3][lr] = b0.w;
        Bs[lk+0][lr+64] = b1.x; Bs[lk+1][lr+64] = b1.y; Bs[lk+2][lr+64] = b1.z; Bs[lk+3][lr+64] = b1.w;
        __syncthreads();

        #pragma unroll
        for (int k = 0; k < KT; k++) {
            float4 aA = *(const float4*)&As[k][ty * 8];
            float4 aB = *(const float4*)&As[k][ty * 8 + 4];
            float4 bA = *(const float4*)&Bs[k][tx * 8];
            float4 bB = *(const float4*)&Bs[k][tx * 8 + 4];
            float av[8] = {aA.x,aA.y,aA.z,aA.w,aB.x,aB.y,aB.z,aB.w};
            float bv[8] = {bA.x,bA.y,bA.z,bA.w,bB.x,bB.y,bB.z,bB.w};
            #pragma unroll
            for (int i = 0; i < 8; i++)
                #pragma unroll
                for (int j = 0; j < 8; j++)
                    acc[i][j] += av[i] * bv[j];
        }
    }

    float* C = g_h + ((size_t)e * T_ + row0) * FF_;
    #pragma unroll
    for (int i = 0; i < 8; i++) {
        int r = ty * 8 + i;
        if (row0 + r < n_e) {
            float4 v0, v1;
            v0.x = acc[i][0] / (1.0f + expf(-acc[i][0]));
            v0.y = acc[i][1] / (1.0f + expf(-acc[i][1]));
            v0.z = acc[i][2] / (1.0f + expf(-acc[i][2]));
            v0.w = acc[i][3] / (1.0f + expf(-acc[i][3]));
            v1.x = acc[i][4] / (1.0f + expf(-acc[i][4]));
            v1.y = acc[i][5] / (1.0f + expf(-acc[i][5]));
            v1.z = acc[i][6] / (1.0f + expf(-acc[i][6]));
            v1.w = acc[i][7] / (1.0f + expf(-acc[i][7]));
            *(float4*)&C[(size_t)r * FF_ + col0 + tx * 8]     = v0;
            *(float4*)&C[(size_t)r * FF_ + col0 + tx * 8 + 4] = v1;
        }
    }
}

// ---------------------------------------------------------------------------
// GEMM2: out[tok(s),n] += wt(s) * ( H[s,:] . W2[e,n,:] )
// ---------------------------------------------------------------------------
__global__ void __launch_bounds__(256, 2)
expert_gemm2(const float* __restrict__ w2, float* __restrict__ out) {
    const int e = blockIdx.z;
    const int n_e = g_cnt[e];
    const int row0 = blockIdx.y * TILE;
    if (row0 >= n_e) return;
    const int col0 = blockIdx.x * TILE;

    __shared__ float As[KT][TILE];
    __shared__ float Bs[KT][TILE];
    __shared__ int   toks[TILE];
    __shared__ float wts[TILE];

    const int tid = threadIdx.x;
    if (tid < TILE) {
        int r = row0 + tid;
        if (r < n_e) { toks[tid] = g_tok[e * T_ + r]; wts[tid] = g_wt[e * T_ + r]; }
        else         { toks[tid] = -1;                wts[tid] = 0.0f; }
    }
    __syncthreads();

    const int lr = tid >> 2;
    const int lk = (tid & 3) * 4;
    const float* Ag = g_h + ((size_t)e * T_ + row0) * FF_;
    const float* arow0 = Ag + (size_t)lr * FF_;
    const float* arow1 = Ag + (size_t)(lr + 64) * FF_;
    const float* Bg = w2 + (size_t)e * D_ * FF_;
    const float* brow0 = Bg + (size_t)(col0 + lr) * FF_;
    const float* brow1 = Bg + (size_t)(col0 + lr + 64) * FF_;

    const int ty = tid >> 4, tx = tid & 15;
    float acc[8][8] = {};

    for (int k0 = 0; k0 < FF_; k0 += KT) {
        float4 a0 = *(const float4*)(arow0 + k0 + lk);
        float4 a1 = *(const float4*)(arow1 + k0 + lk);
        float4 b0 = *(const float4*)(brow0 + k0 + lk);
        float4 b1 = *(const float4*)(brow1 + k0 + lk);

        __syncthreads();
        As[lk+0][lr] = a0.x; As[lk+1][lr] = a0.y; As[lk+2][lr] = a0.z; As[lk+3][lr] = a0.w;
        As[lk+0][lr+64] = a1.x; As[lk+1][lr+64] = a1.y; As[lk+2][lr+64] = a1.z; As[lk+3][lr+64] = a1.w;
        Bs[lk+0][lr] = b0.x; Bs[lk+1][lr] = b0.y; Bs[lk+2][lr] = b0.z; Bs[lk+3][lr] = b0.w;
        Bs[lk+0][lr+64] = b1.x; Bs[lk+1][lr+64] = b1.y; Bs[lk+2][lr+64] = b1.z; Bs[lk+3][lr+64] = b1.w;
        __syncthreads();

        #pragma unroll
        for (int k = 0; k < KT; k++) {
            float4 aA = *(const float4*)&As[k][ty * 8];
            float4 aB = *(const float4*)&As[k][ty * 8 + 4];
            float4 bA = *(const float4*)&Bs[k][tx * 8];
            float4 bB = *(const float4*)&Bs[k][tx * 8 + 4];
            float av[8] = {aA.x,aA.y,aA.z,aA.w,aB.x,aB.y,aB.z,aB.w};
            float bv[8] = {bA.x,bA.y,bA.z,bA.w,bB.x,bB.y,bB.z,bB.w};
            #pragma unroll
            for (int i = 0; i < 8; i++)
                #pragma unroll
                for (int j = 0; j < 8; j++)
                    acc[i][j] += av[i] * bv[j];
        }
    }

    #pragma unroll
    for (int i = 0; i < 8; i++) {
        int r = ty * 8 + i;
        if (row0 + r < n_e) {
            int   t = toks[r];
            float w = wts[r];
            float* orow = out + (size_t)t * D_ + col0 + tx * 8;
            #pragma unroll
            for (int j = 0; j < 8; j++)
                atomicAdd(&orow[j], w * acc[i][j]);
        }
    }
}

// ---------------------------------------------------------------------------
extern "C" void kernel_launch(void* const* d_in, const int* in_sizes, int n_in,
                              void* d_out, int out_size) {
    const float* x  = (const float*)d_in[0];
    const float* rw = (const float*)d_in[1];
    const float* w1 = (const float*)d_in[2];
    const float* w2 = (const float*)d_in[3];
    float* out = (float*)d_out;

    zero_kernel<<<(out_size + 255) / 256, 256>>>(out, out_size);
    router_kernel<<<T_, 256>>>(x, rw, out, out_size);
    expert_gemm1<<<dim3(FF_ / TILE, T_ / TILE, E_), 256>>>(x, w1);
    expert_gemm2<<<dim3(D_ / TILE, T_ / TILE, E_), 256>>>(w2, out);
}

// round 4
// speedup vs baseline: 3.0312x; 2.3521x over previous
#include <cuda_runtime.h>
#include <cuda_bf16.h>
#include <math.h>
#include <stdint.h>

// Problem constants
#define B_   2
#define S_   1024
#define D_   1024
#define E_   8
#define KTOP 2
#define FF_  2048
#define T_   (B_ * S_)
#define OUT_MAIN (T_ * D_)
#define OUT_FULL (OUT_MAIN + T_*E_ + T_*KTOP + T_*KTOP)

// GEMM tiling (mma.sync path)
#define BM 128
#define BN 128
#define BK 32          // K elements per stage
// smem stage: A_hi 8K | A_lo 8K | B_hi 8K | B_lo 8K   (128 rows x 32 bf16 = 64B/row)
#define AH_OFF 0
#define AL_OFF 8192
#define BH_OFF 16384
#define BL_OFF 24576
#define STAGE  32768
#define SOFF_BUF 1024          // toks [0,512), wts [512,1024)
#define SMEM_TOTAL (SOFF_BUF + 2 * STAGE)   // 66560

// Device scratch
__device__ int   g_cnt[E_];
__device__ int   g_tok[E_ * T_];
__device__ float g_wt [E_ * T_];
__device__ __nv_bfloat16 g_h_hi[(size_t)E_ * T_ * FF_];
__device__ __nv_bfloat16 g_h_lo[(size_t)E_ * T_ * FF_];

// ---------------------------------------------------------------------------
// helpers
// ---------------------------------------------------------------------------
__device__ __forceinline__ uint32_t smem_u32(const void* p) {
    uint32_t a;
    asm("{ .reg .u64 t; cvta.to.shared.u64 t, %1; cvt.u32.u64 %0, t; }"
        : "=r"(a) : "l"(p));
    return a;
}

// swizzled byte offset inside a [rows][32 bf16] tile (64B rows, 16B chunks)
__device__ __forceinline__ uint32_t swz(int r, int c) {
    return (uint32_t)(r * 64 + ((c ^ ((r >> 1) & 3)) << 4));
}

__device__ __forceinline__ void ldsm_x4(uint32_t addr, uint32_t r[4]) {
    asm volatile("ldmatrix.sync.aligned.m8n8.x4.shared.b16 {%0,%1,%2,%3}, [%4];"
                 : "=r"(r[0]), "=r"(r[1]), "=r"(r[2]), "=r"(r[3]) : "r"(addr));
}

__device__ __forceinline__ void mma_bf16(float c[4], const uint32_t a[4],
                                         uint32_t b0, uint32_t b1) {
    asm volatile("mma.sync.aligned.m16n8k16.row.col.f32.bf16.bf16.f32 "
                 "{%0,%1,%2,%3}, {%4,%5,%6,%7}, {%8,%9}, {%0,%1,%2,%3};"
                 : "+f"(c[0]), "+f"(c[1]), "+f"(c[2]), "+f"(c[3])
                 : "r"(a[0]), "r"(a[1]), "r"(a[2]), "r"(a[3]),
                   "r"(b0), "r"(b1));
}

// fp32 pair -> bf16x2 hi + residuals
__device__ __forceinline__ uint32_t pack_hi(float a, float b, float& ra, float& rb) {
    __nv_bfloat162 h = __float22bfloat162_rn(make_float2(a, b));
    ra = a - __bfloat162float(h.x);
    rb = b - __bfloat162float(h.y);
    return *reinterpret_cast<uint32_t*>(&h);
}
__device__ __forceinline__ uint32_t pack_bf2(float a, float b) {
    __nv_bfloat162 h = __float22bfloat162_rn(make_float2(a, b));
    return *reinterpret_cast<uint32_t*>(&h);
}

__device__ __forceinline__ void load16(float4 f[4], const float* p) {
    if (p) {
        f[0] = *(const float4*)(p + 0);  f[1] = *(const float4*)(p + 4);
        f[2] = *(const float4*)(p + 8);  f[3] = *(const float4*)(p + 12);
    } else {
        f[0] = f[1] = f[2] = f[3] = make_float4(0.f, 0.f, 0.f, 0.f);
    }
}

// split 16 fp32 into bf16 hi/lo and store swizzled (offA: elems 0..7, offB: 8..15)
__device__ __forceinline__ void split4(char* hi, char* lo,
                                       uint32_t offA, uint32_t offB,
                                       const float4 f[4]) {
    float ra, rb;
    uint4 H, L;
    H.x = pack_hi(f[0].x, f[0].y, ra, rb); L.x = pack_bf2(ra, rb);
    H.y = pack_hi(f[0].z, f[0].w, ra, rb); L.y = pack_bf2(ra, rb);
    H.z = pack_hi(f[1].x, f[1].y, ra, rb); L.z = pack_bf2(ra, rb);
    H.w = pack_hi(f[1].z, f[1].w, ra, rb); L.w = pack_bf2(ra, rb);
    *(uint4*)(hi + offA) = H; *(uint4*)(lo + offA) = L;
    H.x = pack_hi(f[2].x, f[2].y, ra, rb); L.x = pack_bf2(ra, rb);
    H.y = pack_hi(f[2].z, f[2].w, ra, rb); L.y = pack_bf2(ra, rb);
    H.z = pack_hi(f[3].x, f[3].y, ra, rb); L.z = pack_bf2(ra, rb);
    H.w = pack_hi(f[3].z, f[3].w, ra, rb); L.w = pack_bf2(ra, rb);
    *(uint4*)(hi + offB) = H; *(uint4*)(lo + offB) = L;
}

// ---------------------------------------------------------------------------
__global__ void zero_kernel(float* __restrict__ out, int n) {
    int i = blockIdx.x * blockDim.x + threadIdx.x;
    if (i < n) out[i] = 0.0f;
    if (blockIdx.x == 0 && threadIdx.x < E_) g_cnt[threadIdx.x] = 0;
}

// ---------------------------------------------------------------------------
__global__ void router_kernel(const float* __restrict__ x,
                              const float* __restrict__ rw,
                              float* __restrict__ out, int out_size) {
    const int t = blockIdx.x;
    __shared__ float xs[D_];
    __shared__ float logits[E_];

    for (int i = threadIdx.x; i < D_; i += blockDim.x)
        xs[i] = x[(size_t)t * D_ + i];
    __syncthreads();

    const int w = threadIdx.x >> 5;
    const int lane = threadIdx.x & 31;
    float s = 0.0f;
    const float* rwe = rw + (size_t)w * D_;
    for (int k = lane; k < D_; k += 32) s += xs[k] * rwe[k];
    #pragma unroll
    for (int o = 16; o; o >>= 1) s += __shfl_xor_sync(0xffffffffu, s, o);
    if (lane == 0) logits[w] = s;
    __syncthreads();

    if (threadIdx.x == 0) {
        float mx = logits[0];
        #pragma unroll
        for (int e = 1; e < E_; e++) mx = fmaxf(mx, logits[e]);
        float p[E_]; float sum = 0.0f;
        #pragma unroll
        for (int e = 0; e < E_; e++) { p[e] = expf(logits[e] - mx); sum += p[e]; }
        float inv = 1.0f / sum;
        #pragma unroll
        for (int e = 0; e < E_; e++) p[e] *= inv;

        int i0 = 0;
        #pragma unroll
        for (int e = 1; e < E_; e++) if (p[e] > p[i0]) i0 = e;
        int i1 = (i0 == 0) ? 1 : 0;
        #pragma unroll
        for (int e = 0; e < E_; e++) if (e != i0 && p[e] > p[i1]) i1 = e;

        float w0 = p[i0], w1 = p[i1];
        float rinv = 1.0f / (w0 + w1);
        w0 *= rinv; w1 *= rinv;

        int s0 = atomicAdd(&g_cnt[i0], 1);
        g_tok[i0 * T_ + s0] = t; g_wt[i0 * T_ + s0] = w0;
        int s1 = atomicAdd(&g_cnt[i1], 1);
        g_tok[i1 * T_ + s1] = t; g_wt[i1 * T_ + s1] = w1;

        if (out_size >= OUT_FULL) {
            float* probs = out + OUT_MAIN;
            float* idxs  = out + OUT_MAIN + T_ * E_;
            float* wts   = out + OUT_MAIN + T_ * E_ + T_ * KTOP;
            #pragma unroll
            for (int e = 0; e < E_; e++) probs[t * E_ + e] = p[e];
            idxs[t * KTOP + 0] = (float)i0;
            idxs[t * KTOP + 1] = (float)i1;
            wts [t * KTOP + 0] = w0;
            wts [t * KTOP + 1] = w1;
        }
    }
}

// ---------------------------------------------------------------------------
// shared mainloop body: one pipeline stage's MMA phase
// ---------------------------------------------------------------------------
__device__ __forceinline__ void mma_stage(uint32_t base, int a_r, int a_c,
                                          int b_r, int b_c,
                                          float acc[2][8][4]) {
    #pragma unroll
    for (int ks = 0; ks < 2; ks++) {
        uint32_t ah[2][4], al[2][4], bh[4][4], bl[4][4];
        #pragma unroll
        for (int mi = 0; mi < 2; mi++) {
            uint32_t off = swz(a_r + mi * 16, ks * 2 + a_c);
            ldsm_x4(base + AH_OFF + off, ah[mi]);
            ldsm_x4(base + AL_OFF + off, al[mi]);
        }
        #pragma unroll
        for (int nj = 0; nj < 4; nj++) {
            uint32_t off = swz(b_r + nj * 16, ks * 2 + b_c);
            ldsm_x4(base + BH_OFF + off, bh[nj]);
            ldsm_x4(base + BL_OFF + off, bl[nj]);
        }
        #pragma unroll
        for (int mi = 0; mi < 2; mi++)
            #pragma unroll
            for (int nj = 0; nj < 4; nj++)
                #pragma unroll
                for (int h = 0; h < 2; h++) {
                    float* c = acc[mi][nj * 2 + h];
                    mma_bf16(c, ah[mi], bh[nj][h*2], bh[nj][h*2+1]);
                    mma_bf16(c, ah[mi], bl[nj][h*2], bl[nj][h*2+1]);
                    mma_bf16(c, al[mi], bh[nj][h*2], bh[nj][h*2+1]);
                }
    }
}

// ---------------------------------------------------------------------------
// GEMM1: H[s,n] = silu( X[tok(s),:] . W1[e,n,:] ), H stored split bf16 hi/lo
// ---------------------------------------------------------------------------
__global__ void __launch_bounds__(256, 1)
expert_gemm1_mma(const float* __restrict__ x, const float* __restrict__ w1) {
    extern __shared__ char smem[];
    const int e = blockIdx.z;
    const int n_e = g_cnt[e];
    const int row0 = blockIdx.y * BM;
    if (row0 >= n_e) return;
    const int col0 = blockIdx.x * BN;
    const int tid = threadIdx.x, wid = tid >> 5, lane = tid & 31;

    int* toks = (int*)smem;
    if (tid < BM) {
        int r = row0 + tid;
        toks[tid] = (r < n_e) ? g_tok[e * T_ + r] : -1;
    }
    __syncthreads();
    const uint32_t sb = smem_u32(smem);

    // loader role
    const int lr = tid >> 1, lh = tid & 1;
    const int tok = toks[lr];
    const float* aptr = (tok >= 0) ? x + (size_t)tok * D_ + lh * 16 : nullptr;
    const float* bptr = w1 + (size_t)e * FF_ * D_ + (size_t)(col0 + lr) * D_ + lh * 16;
    const uint32_t offA = swz(lr, lh * 2), offB = swz(lr, lh * 2 + 1);

    // mma role
    const int warp_m = wid & 3, warp_n = wid >> 2;
    const int a_r = warp_m * 32 + (lane & 15);
    const int a_c = lane >> 4;
    const int b_r = warp_n * 64 + (lane & 7) + ((lane >> 4) & 1) * 8;
    const int b_c = (lane >> 3) & 1;

    float acc[2][8][4] = {};
    float4 fa[4], fb[4];
    load16(fa, aptr);
    load16(fb, bptr);

    const int S = D_ / BK;
    #pragma unroll 1
    for (int s = 0; s < S; s++) {
        char* bufc = smem + SOFF_BUF + (s & 1) * STAGE;
        split4(bufc + AH_OFF, bufc + AL_OFF, offA, offB, fa);
        split4(bufc + BH_OFF, bufc + BL_OFF, offA, offB, fb);
        __syncthreads();
        if (s + 1 < S) {
            load16(fa, aptr ? aptr + (s + 1) * BK : nullptr);
            load16(fb, bptr + (s + 1) * BK);
        }
        mma_stage(sb + SOFF_BUF + (s & 1) * STAGE, a_r, a_c, b_r, b_c, acc);
    }

    // epilogue: silu -> split bf16 -> g_h
    const int g = lane >> 2, tq = lane & 3;
    #pragma unroll
    for (int mi = 0; mi < 2; mi++) {
        const int rA = row0 + warp_m * 32 + mi * 16 + g;
        const int rB = rA + 8;
        #pragma unroll
        for (int u = 0; u < 8; u++) {
            const int col = col0 + warp_n * 64 + u * 8 + tq * 2;
            float ra, rb;
            if (rA < n_e) {
                float a = acc[mi][u][0], b = acc[mi][u][1];
                a = a / (1.0f + __expf(-a));
                b = b / (1.0f + __expf(-b));
                uint32_t hi = pack_hi(a, b, ra, rb);
                uint32_t lo = pack_bf2(ra, rb);
                size_t idx = ((size_t)e * T_ + rA) * FF_ + col;
                *(uint32_t*)(g_h_hi + idx) = hi;
                *(uint32_t*)(g_h_lo + idx) = lo;
            }
            if (rB < n_e) {
                float a = acc[mi][u][2], b = acc[mi][u][3];
                a = a / (1.0f + __expf(-a));
                b = b / (1.0f + __expf(-b));
                uint32_t hi = pack_hi(a, b, ra, rb);
                uint32_t lo = pack_bf2(ra, rb);
                size_t idx = ((size_t)e * T_ + rB) * FF_ + col;
                *(uint32_t*)(g_h_hi + idx) = hi;
                *(uint32_t*)(g_h_lo + idx) = lo;
            }
        }
    }
}

// ---------------------------------------------------------------------------
// GEMM2: out[tok(s),n] += wt(s) * ( H[s,:] . W2[e,n,:] )
// ---------------------------------------------------------------------------
__global__ void __launch_bounds__(256, 1)
expert_gemm2_mma(const float* __restrict__ w2, float* __restrict__ out) {
    extern __shared__ char smem[];
    const int e = blockIdx.z;
    const int n_e = g_cnt[e];
    const int row0 = blockIdx.y * BM;
    if (row0 >= n_e) return;
    const int col0 = blockIdx.x * BN;
    const int tid = threadIdx.x, wid = tid >> 5, lane = tid & 31;

    int*   toks = (int*)smem;
    float* wts  = (float*)(smem + 512);
    if (tid < BM) {
        int r = row0 + tid;
        if (r < n_e) { toks[tid] = g_tok[e * T_ + r]; wts[tid] = g_wt[e * T_ + r]; }
        else         { toks[tid] = 0;                 wts[tid] = 0.0f; }
    }
    __syncthreads();
    const uint32_t sb = smem_u32(smem);

    // loader role
    const int lr = tid >> 1, lh = tid & 1;
    const size_t arow = (size_t)e * T_ + row0 + lr;
    const __nv_bfloat16* ahp = g_h_hi + arow * FF_ + lh * 16;
    const __nv_bfloat16* alp = g_h_lo + arow * FF_ + lh * 16;
    const float* bptr = w2 + (size_t)e * D_ * FF_ + (size_t)(col0 + lr) * FF_ + lh * 16;
    const uint32_t offA = swz(lr, lh * 2), offB = swz(lr, lh * 2 + 1);

    // mma role
    const int warp_m = wid & 3, warp_n = wid >> 2;
    const int a_r = warp_m * 32 + (lane & 15);
    const int a_c = lane >> 4;
    const int b_r = warp_n * 64 + (lane & 7) + ((lane >> 4) & 1) * 8;
    const int b_c = (lane >> 3) & 1;

    float acc[2][8][4] = {};
    uint4 h0, h1, l0, l1;
    float4 fb[4];
    h0 = *(const uint4*)(ahp);     h1 = *((const uint4*)(ahp) + 1);
    l0 = *(const uint4*)(alp);     l1 = *((const uint4*)(alp) + 1);
    load16(fb, bptr);

    const int S = FF_ / BK;
    #pragma unroll 1
    for (int s = 0; s < S; s++) {
        char* bufc = smem + SOFF_BUF + (s & 1) * STAGE;
        *(uint4*)(bufc + AH_OFF + offA) = h0;
        *(uint4*)(bufc + AH_OFF + offB) = h1;
        *(uint4*)(bufc + AL_OFF + offA) = l0;
        *(uint4*)(bufc + AL_OFF + offB) = l1;
        split4(bufc + BH_OFF, bufc + BL_OFF, offA, offB, fb);
        __syncthreads();
        if (s + 1 < S) {
            const int k1 = (s + 1) * BK;
            h0 = *(const uint4*)(ahp + k1);  h1 = *((const uint4*)(ahp + k1) + 1);
            l0 = *(const uint4*)(alp + k1);  l1 = *((const uint4*)(alp + k1) + 1);
            load16(fb, bptr + k1);
        }
        mma_stage(sb + SOFF_BUF + (s & 1) * STAGE, a_r, a_c, b_r, b_c, acc);
    }

    // epilogue: weighted atomic scatter
    const int g = lane >> 2, tq = lane & 3;
    #pragma unroll
    for (int mi = 0; mi < 2; mi++) {
        const int rlA = warp_m * 32 + mi * 16 + g;
        const int rlB = rlA + 8;
        #pragma unroll
        for (int u = 0; u < 8; u++) {
            const int col = col0 + warp_n * 64 + u * 8 + tq * 2;
            if (row0 + rlA < n_e) {
                float w = wts[rlA];
                float* o = out + (size_t)toks[rlA] * D_ + col;
                atomicAdd(o,     w * acc[mi][u][0]);
                atomicAdd(o + 1, w * acc[mi][u][1]);
            }
            if (row0 + rlB < n_e) {
                float w = wts[rlB];
                float* o = out + (size_t)toks[rlB] * D_ + col;
                atomicAdd(o,     w * acc[mi][u][2]);
                atomicAdd(o + 1, w * acc[mi][u][3]);
            }
        }
    }
}

// ---------------------------------------------------------------------------
extern "C" void kernel_launch(void* const* d_in, const int* in_sizes, int n_in,
                              void* d_out, int out_size) {
    const float* x  = (const float*)d_in[0];
    const float* rw = (const float*)d_in[1];
    const float* w1 = (const float*)d_in[2];
    const float* w2 = (const float*)d_in[3];
    float* out = (float*)d_out;

    cudaFuncSetAttribute(expert_gemm1_mma,
                         cudaFuncAttributeMaxDynamicSharedMemorySize, SMEM_TOTAL);
    cudaFuncSetAttribute(expert_gemm2_mma,
                         cudaFuncAttributeMaxDynamicSharedMemorySize, SMEM_TOTAL);

    zero_kernel<<<(out_size + 255) / 256, 256>>>(out, out_size);
    router_kernel<<<T_, 256>>>(x, rw, out, out_size);
    expert_gemm1_mma<<<dim3(FF_ / BN, T_ / BM, E_), 256, SMEM_TOTAL>>>(x, w1);
    expert_gemm2_mma<<<dim3(D_ / BN, T_ / BM, E_), 256, SMEM_TOTAL>>>(w2, out);
}

// round 5
// speedup vs baseline: 3.2800x; 1.0821x over previous
#include <cuda_runtime.h>
#include <cuda_bf16.h>
#include <math.h>
#include <stdint.h>

// Problem constants
#define B_   2
#define S_   1024
#define D_   1024
#define E_   8
#define KTOP 2
#define FF_  2048
#define T_   (B_ * S_)
#define OUT_MAIN (T_ * D_)
#define OUT_FULL (OUT_MAIN + T_*E_ + T_*KTOP + T_*KTOP)

// GEMM tiling (mma.sync path), 512 threads / 16 warps, warp tile 32x32
#define BM 128
#define BN 128
#define BK 32
#define AH_OFF 0
#define AL_OFF 8192
#define BH_OFF 16384
#define BL_OFF 24576
#define STAGE  32768
#define SOFF_BUF 1024          // toks [0,512), wts [512,1024)
#define SMEM_TOTAL (SOFF_BUF + 2 * STAGE)   // 66560

// Device scratch
__device__ int   g_cnt[E_];
__device__ int   g_tok[E_ * T_];
__device__ float g_wt [E_ * T_];
__device__ __nv_bfloat16 g_h_hi[(size_t)E_ * T_ * FF_];
__device__ __nv_bfloat16 g_h_lo[(size_t)E_ * T_ * FF_];

// ---------------------------------------------------------------------------
__device__ __forceinline__ uint32_t smem_u32(const void* p) {
    uint32_t a;
    asm("{ .reg .u64 t; cvta.to.shared.u64 t, %1; cvt.u32.u64 %0, t; }"
        : "=r"(a) : "l"(p));
    return a;
}

// swizzled byte offset inside a [rows][32 bf16] tile (64B rows, 16B chunks)
__device__ __forceinline__ uint32_t swz(int r, int c) {
    return (uint32_t)(r * 64 + ((c ^ ((r >> 1) & 3)) << 4));
}

__device__ __forceinline__ void ldsm_x4(uint32_t addr, uint32_t r[4]) {
    asm volatile("ldmatrix.sync.aligned.m8n8.x4.shared.b16 {%0,%1,%2,%3}, [%4];"
                 : "=r"(r[0]), "=r"(r[1]), "=r"(r[2]), "=r"(r[3]) : "r"(addr));
}

__device__ __forceinline__ void mma_bf16(float c[4], const uint32_t a[4],
                                         uint32_t b0, uint32_t b1) {
    asm volatile("mma.sync.aligned.m16n8k16.row.col.f32.bf16.bf16.f32 "
                 "{%0,%1,%2,%3}, {%4,%5,%6,%7}, {%8,%9}, {%0,%1,%2,%3};"
                 : "+f"(c[0]), "+f"(c[1]), "+f"(c[2]), "+f"(c[3])
                 : "r"(a[0]), "r"(a[1]), "r"(a[2]), "r"(a[3]),
                   "r"(b0), "r"(b1));
}

__device__ __forceinline__ uint32_t pack_hi(float a, float b, float& ra, float& rb) {
    __nv_bfloat162 h = __float22bfloat162_rn(make_float2(a, b));
    ra = a - __bfloat162float(h.x);
    rb = b - __bfloat162float(h.y);
    return *reinterpret_cast<uint32_t*>(&h);
}
__device__ __forceinline__ uint32_t pack_bf2(float a, float b) {
    __nv_bfloat162 h = __float22bfloat162_rn(make_float2(a, b));
    return *reinterpret_cast<uint32_t*>(&h);
}

__device__ __forceinline__ void load8(float4 f[2], const float* p) {
    if (p) { f[0] = *(const float4*)p; f[1] = *(const float4*)(p + 4); }
    else   { f[0] = f[1] = make_float4(0.f, 0.f, 0.f, 0.f); }
}

// split 8 fp32 -> one 16B hi chunk + one 16B lo chunk at off
__device__ __forceinline__ void split8(char* hi, char* lo, uint32_t off,
                                       const float4 f[2]) {
    float ra, rb;
    uint4 H, L;
    H.x = pack_hi(f[0].x, f[0].y, ra, rb); L.x = pack_bf2(ra, rb);
    H.y = pack_hi(f[0].z, f[0].w, ra, rb); L.y = pack_bf2(ra, rb);
    H.z = pack_hi(f[1].x, f[1].y, ra, rb); L.z = pack_bf2(ra, rb);
    H.w = pack_hi(f[1].z, f[1].w, ra, rb); L.w = pack_bf2(ra, rb);
    *(uint4*)(hi + off) = H; *(uint4*)(lo + off) = L;
}

// ---------------------------------------------------------------------------
__global__ void zero_kernel(float* __restrict__ out, int n) {
    int i = blockIdx.x * blockDim.x + threadIdx.x;
    if (i < n) out[i] = 0.0f;
    if (blockIdx.x == 0 && threadIdx.x < E_) g_cnt[threadIdx.x] = 0;
}

// ---------------------------------------------------------------------------
__global__ void router_kernel(const float* __restrict__ x,
                              const float* __restrict__ rw,
                              float* __restrict__ out, int out_size) {
    const int t = blockIdx.x;
    __shared__ float xs[D_];
    __shared__ float logits[E_];

    for (int i = threadIdx.x; i < D_; i += blockDim.x)
        xs[i] = x[(size_t)t * D_ + i];
    __syncthreads();

    const int w = threadIdx.x >> 5;
    const int lane = threadIdx.x & 31;
    float s = 0.0f;
    const float* rwe = rw + (size_t)w * D_;
    for (int k = lane; k < D_; k += 32) s += xs[k] * rwe[k];
    #pragma unroll
    for (int o = 16; o; o >>= 1) s += __shfl_xor_sync(0xffffffffu, s, o);
    if (lane == 0) logits[w] = s;
    __syncthreads();

    if (threadIdx.x == 0) {
        float mx = logits[0];
        #pragma unroll
        for (int e = 1; e < E_; e++) mx = fmaxf(mx, logits[e]);
        float p[E_]; float sum = 0.0f;
        #pragma unroll
        for (int e = 0; e < E_; e++) { p[e] = expf(logits[e] - mx); sum += p[e]; }
        float inv = 1.0f / sum;
        #pragma unroll
        for (int e = 0; e < E_; e++) p[e] *= inv;

        int i0 = 0;
        #pragma unroll
        for (int e = 1; e < E_; e++) if (p[e] > p[i0]) i0 = e;
        int i1 = (i0 == 0) ? 1 : 0;
        #pragma unroll
        for (int e = 0; e < E_; e++) if (e != i0 && p[e] > p[i1]) i1 = e;

        float w0 = p[i0], w1 = p[i1];
        float rinv = 1.0f / (w0 + w1);
        w0 *= rinv; w1 *= rinv;

        int s0 = atomicAdd(&g_cnt[i0], 1);
        g_tok[i0 * T_ + s0] = t; g_wt[i0 * T_ + s0] = w0;
        int s1 = atomicAdd(&g_cnt[i1], 1);
        g_tok[i1 * T_ + s1] = t; g_wt[i1 * T_ + s1] = w1;

        if (out_size >= OUT_FULL) {
            float* probs = out + OUT_MAIN;
            float* idxs  = out + OUT_MAIN + T_ * E_;
            float* wts   = out + OUT_MAIN + T_ * E_ + T_ * KTOP;
            #pragma unroll
            for (int e = 0; e < E_; e++) probs[t * E_ + e] = p[e];
            idxs[t * KTOP + 0] = (float)i0;
            idxs[t * KTOP + 1] = (float)i1;
            wts [t * KTOP + 0] = w0;
            wts [t * KTOP + 1] = w1;
        }
    }
}

// ---------------------------------------------------------------------------
// one pipeline stage's MMA phase: warp tile 32x32 (mi 0..1, nj 0..1)
// ---------------------------------------------------------------------------
__device__ __forceinline__ void mma_stage(uint32_t base, int a_r, int a_c,
                                          int b_r, int b_c,
                                          float acc[2][4][4]) {
    #pragma unroll
    for (int ks = 0; ks < 2; ks++) {
        uint32_t ah[2][4], al[2][4], bh[2][4], bl[2][4];
        #pragma unroll
        for (int mi = 0; mi < 2; mi++) {
            uint32_t off = swz(a_r + mi * 16, ks * 2 + a_c);
            ldsm_x4(base + AH_OFF + off, ah[mi]);
            ldsm_x4(base + AL_OFF + off, al[mi]);
        }
        #pragma unroll
        for (int nj = 0; nj < 2; nj++) {
            uint32_t off = swz(b_r + nj * 16, ks * 2 + b_c);
            ldsm_x4(base + BH_OFF + off, bh[nj]);
            ldsm_x4(base + BL_OFF + off, bl[nj]);
        }
        #pragma unroll
        for (int mi = 0; mi < 2; mi++)
            #pragma unroll
            for (int nj = 0; nj < 2; nj++)
                #pragma unroll
                for (int h = 0; h < 2; h++) {
                    float* c = acc[mi][nj * 2 + h];
                    mma_bf16(c, ah[mi], bh[nj][h*2], bh[nj][h*2+1]);
                    mma_bf16(c, ah[mi], bl[nj][h*2], bl[nj][h*2+1]);
                    mma_bf16(c, al[mi], bh[nj][h*2], bh[nj][h*2+1]);
                }
    }
}

// ---------------------------------------------------------------------------
// GEMM1: H[s,n] = silu( X[tok(s),:] . W1[e,n,:] ), H stored split bf16 hi/lo
// ---------------------------------------------------------------------------
__global__ void __launch_bounds__(512, 1)
expert_gemm1_mma(const float* __restrict__ x, const float* __restrict__ w1) {
    extern __shared__ char smem[];
    const int e = blockIdx.z;
    const int n_e = g_cnt[e];
    const int row0 = blockIdx.y * BM;
    if (row0 >= n_e) return;
    const int col0 = blockIdx.x * BN;
    const int tid = threadIdx.x, wid = tid >> 5, lane = tid & 31;

    int* toks = (int*)smem;
    if (tid < BM) {
        int r = row0 + tid;
        toks[tid] = (r < n_e) ? g_tok[e * T_ + r] : -1;
    }
    __syncthreads();
    const uint32_t sb = smem_u32(smem);

    // loader role: 4 threads per row, 8 fp32 each
    const int lr = tid >> 2, q = tid & 3;
    const int tok = toks[lr];
    const float* aptr = (tok >= 0) ? x + (size_t)tok * D_ + q * 8 : nullptr;
    const float* bptr = w1 + (size_t)e * FF_ * D_ + (size_t)(col0 + lr) * D_ + q * 8;
    const uint32_t off = swz(lr, q);

    // mma role: 4x4 warp grid, warp tile 32x32
    const int warp_m = wid & 3, warp_n = wid >> 2;
    const int a_r = warp_m * 32 + (lane & 15);
    const int a_c = lane >> 4;
    const int b_r = warp_n * 32 + (lane & 7) + ((lane >> 4) & 1) * 8;
    const int b_c = (lane >> 3) & 1;

    float acc[2][4][4] = {};
    float4 fa[2], fb[2];
    load8(fa, aptr);
    load8(fb, bptr);

    const int S = D_ / BK;
    #pragma unroll 1
    for (int s = 0; s < S; s++) {
        char* bufc = smem + SOFF_BUF + (s & 1) * STAGE;
        split8(bufc + AH_OFF, bufc + AL_OFF, off, fa);
        split8(bufc + BH_OFF, bufc + BL_OFF, off, fb);
        __syncthreads();
        if (s + 1 < S) {
            load8(fa, aptr ? aptr + (s + 1) * BK : nullptr);
            load8(fb, bptr + (s + 1) * BK);
        }
        mma_stage(sb + SOFF_BUF + (s & 1) * STAGE, a_r, a_c, b_r, b_c, acc);
    }

    // epilogue: silu -> split bf16 -> g_h
    const int g = lane >> 2, tq = lane & 3;
    #pragma unroll
    for (int mi = 0; mi < 2; mi++) {
        const int rA = row0 + warp_m * 32 + mi * 16 + g;
        const int rB = rA + 8;
        #pragma unroll
        for (int u = 0; u < 4; u++) {
            const int col = col0 + warp_n * 32 + u * 8 + tq * 2;
            float ra, rb;
            if (rA < n_e) {
                float a = acc[mi][u][0], b = acc[mi][u][1];
                a = a / (1.0f + __expf(-a));
                b = b / (1.0f + __expf(-b));
                uint32_t hi = pack_hi(a, b, ra, rb);
                uint32_t lo = pack_bf2(ra, rb);
                size_t idx = ((size_t)e * T_ + rA) * FF_ + col;
                *(uint32_t*)(g_h_hi + idx) = hi;
                *(uint32_t*)(g_h_lo + idx) = lo;
            }
            if (rB < n_e) {
                float a = acc[mi][u][2], b = acc[mi][u][3];
                a = a / (1.0f + __expf(-a));
                b = b / (1.0f + __expf(-b));
                uint32_t hi = pack_hi(a, b, ra, rb);
                uint32_t lo = pack_bf2(ra, rb);
                size_t idx = ((size_t)e * T_ + rB) * FF_ + col;
                *(uint32_t*)(g_h_hi + idx) = hi;
                *(uint32_t*)(g_h_lo + idx) = lo;
            }
        }
    }
}

// ---------------------------------------------------------------------------
// GEMM2: out[tok(s),n] += wt(s) * ( H[s,:] . W2[e,n,:] )
// ---------------------------------------------------------------------------
__global__ void __launch_bounds__(512, 1)
expert_gemm2_mma(const float* __restrict__ w2, float* __restrict__ out) {
    extern __shared__ char smem[];
    const int e = blockIdx.z;
    const int n_e = g_cnt[e];
    const int row0 = blockIdx.y * BM;
    if (row0 >= n_e) return;
    const int col0 = blockIdx.x * BN;
    const int tid = threadIdx.x, wid = tid >> 5, lane = tid & 31;

    int*   toks = (int*)smem;
    float* wts  = (float*)(smem + 512);
    if (tid < BM) {
        int r = row0 + tid;
        if (r < n_e) { toks[tid] = g_tok[e * T_ + r]; wts[tid] = g_wt[e * T_ + r]; }
        else         { toks[tid] = 0;                 wts[tid] = 0.0f; }
    }
    __syncthreads();
    const uint32_t sb = smem_u32(smem);

    // loader role
    const int lr = tid >> 2, q = tid & 3;
    const size_t arow = (size_t)e * T_ + row0 + lr;
    const __nv_bfloat16* ahp = g_h_hi + arow * FF_ + q * 8;
    const __nv_bfloat16* alp = g_h_lo + arow * FF_ + q * 8;
    const float* bptr = w2 + (size_t)e * D_ * FF_ + (size_t)(col0 + lr) * FF_ + q * 8;
    const uint32_t off = swz(lr, q);

    // mma role
    const int warp_m = wid & 3, warp_n = wid >> 2;
    const int a_r = warp_m * 32 + (lane & 15);
    const int a_c = lane >> 4;
    const int b_r = warp_n * 32 + (lane & 7) + ((lane >> 4) & 1) * 8;
    const int b_c = (lane >> 3) & 1;

    float acc[2][4][4] = {};
    uint4 h0, l0;
    float4 fb[2];
    h0 = *(const uint4*)ahp;
    l0 = *(const uint4*)alp;
    load8(fb, bptr);

    const int S = FF_ / BK;
    #pragma unroll 1
    for (int s = 0; s < S; s++) {
        char* bufc = smem + SOFF_BUF + (s & 1) * STAGE;
        *(uint4*)(bufc + AH_OFF + off) = h0;
        *(uint4*)(bufc + AL_OFF + off) = l0;
        split8(bufc + BH_OFF, bufc + BL_OFF, off, fb);
        __syncthreads();
        if (s + 1 < S) {
            const int k1 = (s + 1) * BK;
            h0 = *(const uint4*)(ahp + k1);
            l0 = *(const uint4*)(alp + k1);
            load8(fb, bptr + k1);
        }
        mma_stage(sb + SOFF_BUF + (s & 1) * STAGE, a_r, a_c, b_r, b_c, acc);
    }

    // epilogue: weighted atomic scatter
    const int g = lane >> 2, tq = lane & 3;
    #pragma unroll
    for (int mi = 0; mi < 2; mi++) {
        const int rlA = warp_m * 32 + mi * 16 + g;
        const int rlB = rlA + 8;
        #pragma unroll
        for (int u = 0; u < 4; u++) {
            const int col = col0 + warp_n * 32 + u * 8 + tq * 2;
            if (row0 + rlA < n_e) {
                float w = wts[rlA];
                float* o = out + (size_t)toks[rlA] * D_ + col;
                atomicAdd(o,     w * acc[mi][u][0]);
                atomicAdd(o + 1, w * acc[mi][u][1]);
            }
            if (row0 + rlB < n_e) {
                float w = wts[rlB];
                float* o = out + (size_t)toks[rlB] * D_ + col;
                atomicAdd(o,     w * acc[mi][u][2]);
                atomicAdd(o + 1, w * acc[mi][u][3]);
            }
        }
    }
}

// ---------------------------------------------------------------------------
extern "C" void kernel_launch(void* const* d_in, const int* in_sizes, int n_in,
                              void* d_out, int out_size) {
    const float* x  = (const float*)d_in[0];
    const float* rw = (const float*)d_in[1];
    const float* w1 = (const float*)d_in[2];
    const float* w2 = (const float*)d_in[3];
    float* out = (float*)d_out;

    cudaFuncSetAttribute(expert_gemm1_mma,
                         cudaFuncAttributeMaxDynamicSharedMemorySize, SMEM_TOTAL);
    cudaFuncSetAttribute(expert_gemm2_mma,
                         cudaFuncAttributeMaxDynamicSharedMemorySize, SMEM_TOTAL);

    zero_kernel<<<(out_size + 255) / 256, 256>>>(out, out_size);
    router_kernel<<<T_, 256>>>(x, rw, out, out_size);
    expert_gemm1_mma<<<dim3(FF_ / BN, T_ / BM, E_), 512, SMEM_TOTAL>>>(x, w1);
    expert_gemm2_mma<<<dim3(D_ / BN, T_ / BM, E_), 512, SMEM_TOTAL>>>(w2, out);
}